// round 16
// baseline (speedup 1.0000x reference)
#include <cuda_runtime.h>
#include <cuda_fp16.h>
#include <math.h>

#define SEQ  512
#define PREV 512
#define TOT  1024
#define BSZ  8
#define DIN  1024
#define NH   16
#define HD   64

// ---------------- scratch (static device globals; no allocations) ----------------
__device__ __half g_in16 [SEQ * BSZ * DIN];
__device__ __half g_mem16[PREV * BSZ * DIN];
__device__ __half g_pos16[TOT * DIN];
__device__ __half g_wkv16[DIN * 2 * DIN];
__device__ __half g_wq16 [DIN * DIN];
__device__ __half g_wp16 [DIN * DIN];
__device__ __half g_wo16 [DIN * DIN];
__device__ __half g_kh [TOT * BSZ * DIN];
__device__ __half g_vh [TOT * BSZ * DIN];
__device__ __half g_ph [TOT * DIN];
__device__ __half g_qu [SEQ * BSZ * DIN];
__device__ __half g_qv [SEQ * BSZ * DIN];
__device__ __half g_awv[SEQ * BSZ * DIN];
__device__ float  g_out[SEQ * BSZ * DIN];

__device__ __forceinline__ unsigned smem_u32(const void* p) {
    return (unsigned)__cvta_generic_to_shared(p);
}
__device__ __forceinline__ void cp16(unsigned dst, const void* src) {
    asm volatile("cp.async.cg.shared.global [%0], [%1], 16;" :: "r"(dst), "l"(src));
}
#define CP_COMMIT() asm volatile("cp.async.commit_group;")
#define CP_WAIT1()  asm volatile("cp.async.wait_group 1;")
#define CP_WAIT2()  asm volatile("cp.async.wait_group 2;")

#define MMA_F16(c, a, b)                                                       \
    asm volatile(                                                              \
        "mma.sync.aligned.m16n8k16.row.col.f32.f16.f16.f32 "                   \
        "{%0,%1,%2,%3},{%4,%5,%6,%7},{%8,%9},{%0,%1,%2,%3};"                   \
        : "+f"(c[0]), "+f"(c[1]), "+f"(c[2]), "+f"(c[3])                       \
        : "r"(a[0]), "r"(a[1]), "r"(a[2]), "r"(a[3]), "r"(b[0]), "r"(b[1]))

__device__ __forceinline__ void ldmx4t(unsigned& r0, unsigned& r1,
                                       unsigned& r2, unsigned& r3, unsigned a) {
    asm volatile("ldmatrix.sync.aligned.m8n8.x4.trans.shared.b16 "
                 "{%0,%1,%2,%3}, [%4];"
                 : "=r"(r0), "=r"(r1), "=r"(r2), "=r"(r3) : "r"(a));
}
__device__ __forceinline__ void ldmx4(unsigned& r0, unsigned& r1,
                                      unsigned& r2, unsigned& r3, unsigned a) {
    asm volatile("ldmatrix.sync.aligned.m8n8.x4.shared.b16 "
                 "{%0,%1,%2,%3}, [%4];"
                 : "=r"(r0), "=r"(r1), "=r"(r2), "=r"(r3) : "r"(a));
}

// ---------------- fp32 -> fp16 converter (single segmented launch) --------------
struct CvtSegs {
    const float4* src[7];
    __half2*      dst[7];
    int           n4[7];
};

__global__ void cvt_all(CvtSegs s)
{
    int i = blockIdx.x * blockDim.x + threadIdx.x;
#pragma unroll
    for (int k = 0; k < 7; k++) {
        if (i < s.n4[k]) {
            float4 v = s.src[k][i];
            s.dst[k][2 * i]     = __floats2half2_rn(v.x, v.y);
            s.dst[k][2 * i + 1] = __floats2half2_rn(v.z, v.w);
            return;
        }
        i -= s.n4[k];
    }
}

extern __shared__ char dsm[];

// GEMM tiles: 256(M) x 128(N), BK=32, 512 threads, 1 block/SM.
// A stage: 256 rows x 80 B (16-aligned, ldmatrix conflict-free).
// B stage: 32 rows x 272 B. 4 pipeline stages, prefetch distance 2.
#define AST 80
#define A_STAGE (256 * AST)    // 20480
#define B_STAGE (32 * 272)     // 8704
#define GEMM_SM (4 * (A_STAGE + B_STAGE))   // 116736

// ============ mega projection GEMM: kv + q + p in ONE launch =====================
// blockIdx.x < 512 : kv  (M=8192 gather(mem|in), N=2048, split -> kh|vh)
// 512..639         : q   (M=4096 in,            N=1024, dual bias -> qu,qv)
// 640..671         : p   (M=1024 pos,           N=1024, plain -> ph)
__global__ __launch_bounds__(512, 1) void proj_mega(
    const __half* __restrict__ in16, const __half* __restrict__ mem16,
    const __half* __restrict__ pos16,
    const __half* __restrict__ wkv, const __half* __restrict__ wq,
    const __half* __restrict__ wp,
    __half* __restrict__ kh, __half* __restrict__ vh,
    __half* __restrict__ quo, __half* __restrict__ qvo,
    __half* __restrict__ ph,
    const float* __restrict__ ubias, const float* __restrict__ vbias)
{
    const int bx = blockIdx.x;
    const __half *A0, *A1, *B;
    int M0, row0, col0, epi;
    long ldb;
    if (bx < 512) {
        row0 = (bx >> 4) * 256; col0 = (bx & 15) * 128;
        A0 = mem16; A1 = in16; M0 = PREV * BSZ; B = wkv; ldb = 2 * DIN; epi = 1;
    } else if (bx < 640) {
        const int t = bx - 512;
        row0 = (t >> 3) * 256; col0 = (t & 7) * 128;
        A0 = in16; A1 = in16; M0 = 1 << 30; B = wq; ldb = DIN; epi = 2;
    } else {
        const int t = bx - 640;
        row0 = (t >> 3) * 256; col0 = (t & 7) * 128;
        A0 = pos16; A1 = pos16; M0 = 1 << 30; B = wp; ldb = DIN; epi = 3;
    }

    const int tid  = threadIdx.x;
    const int lane = tid & 31, wid = tid >> 5;
    const int gid  = lane >> 2, tig = lane & 3;
    const int warp_m = (wid & 7) * 32;
    const int warp_n = (wid >> 3) * 64;

    char* As = dsm;                   // 4 x A_STAGE
    char* Bs = dsm + 4 * A_STAGE;     // 4 x B_STAGE

    float c[2][8][4];
#pragma unroll
    for (int mt = 0; mt < 2; mt++)
#pragma unroll
        for (int nt = 0; nt < 8; nt++)
#pragma unroll
            for (int q = 0; q < 4; q++) c[mt][nt][q] = 0.f;

    auto issue = [&](int k0, int buf) {
        unsigned ab = smem_u32(As + buf * A_STAGE);
        unsigned bb = smem_u32(Bs + buf * B_STAGE);
#pragma unroll
        for (int it = 0; it < 2; it++) {          // A: 256 rows x 4 chunks
            const int f = tid + it * 512;
            const int r = f >> 2, u = f & 3;
            const int gm = row0 + r;
            const __half* src = (gm < M0 ? A0 + (size_t)gm * DIN
                                         : A1 + (size_t)(gm - M0) * DIN) + k0 + u * 8;
            cp16(ab + r * AST + u * 16, src);
        }
        {                                          // B: 32 k x 128 n
            const int k = tid >> 4, u = tid & 15;
            cp16(bb + k * 272 + u * 16, B + (size_t)(k0 + k) * ldb + col0 + u * 8);
        }
    };

    issue(0, 0);  CP_COMMIT();
    issue(32, 1); CP_COMMIT();

    const int lrow = (lane & 7) + ((lane >> 3) & 1) * 8;
    const int lcol = ((lane >> 4) & 1) * 8;
    const int aoff = (warp_m + (lane & 15)) * AST + (lane >> 4) * 16;

    for (int kt = 0; kt < 32; kt++) {
        if (kt + 2 < 32) issue((kt + 2) * 32, (kt + 2) & 3);
        CP_COMMIT();
        CP_WAIT2();
        __syncthreads();

        const unsigned ab = smem_u32(As + (kt & 3) * A_STAGE);
        const unsigned bb = smem_u32(Bs + (kt & 3) * B_STAGE);
#pragma unroll
        for (int kc = 0; kc < 2; kc++) {
            unsigned a[2][4];
#pragma unroll
            for (int mt = 0; mt < 2; mt++)
                ldmx4(a[mt][0], a[mt][1], a[mt][2], a[mt][3],
                      ab + aoff + mt * 16 * AST + kc * 32);
#pragma unroll
            for (int p = 0; p < 4; p++) {
                unsigned r0, r1, r2, r3;
                ldmx4t(r0, r1, r2, r3,
                       bb + (kc * 16 + lrow) * 272 + (warp_n + p * 16 + lcol) * 2);
                unsigned b0[2] = {r0, r1}, b1[2] = {r2, r3};
#pragma unroll
                for (int mt = 0; mt < 2; mt++) {
                    MMA_F16(c[mt][2 * p],     a[mt], b0);
                    MMA_F16(c[mt][2 * p + 1], a[mt], b1);
                }
            }
        }
    }

#pragma unroll
    for (int mt = 0; mt < 2; mt++) {
#pragma unroll
        for (int nt = 0; nt < 8; nt++) {
            const int cb = col0 + warp_n + nt * 8 + 2 * tig;
#pragma unroll
            for (int hf = 0; hf < 2; hf++) {
                const int r = row0 + warp_m + mt * 16 + gid + 8 * hf;
                float v0 = c[mt][nt][hf * 2], v1 = c[mt][nt][hf * 2 + 1];
                if (epi == 1) {
                    __half2 h = __floats2half2_rn(v0, v1);
                    if (cb < DIN)
                        *(__half2*)(kh + (size_t)r * DIN + cb) = h;
                    else
                        *(__half2*)(vh + (size_t)r * DIN + cb - DIN) = h;
                } else if (epi == 2) {
                    *(__half2*)(quo + (size_t)r * DIN + cb) =
                        __floats2half2_rn(v0 + ubias[cb], v1 + ubias[cb + 1]);
                    *(__half2*)(qvo + (size_t)r * DIN + cb) =
                        __floats2half2_rn(v0 + vbias[cb], v1 + vbias[cb + 1]);
                } else {
                    *(__half2*)(ph + (size_t)r * DIN + cb) =
                        __floats2half2_rn(v0, v1);
                }
            }
        }
    }
}

// ============ output projection GEMM (fp32 out + residual), same scheme ==========
__global__ __launch_bounds__(512, 1) void out_gemm(
    const __half* __restrict__ A, const __half* __restrict__ B,
    float* __restrict__ O, const float* __restrict__ resid)
{
    const int tid  = threadIdx.x;
    const int lane = tid & 31, wid = tid >> 5;
    const int gid  = lane >> 2, tig = lane & 3;
    const int warp_m = (wid & 7) * 32;
    const int warp_n = (wid >> 3) * 64;
    const int row0 = blockIdx.y * 256;
    const int col0 = blockIdx.x * 128;

    char* As = dsm;
    char* Bs = dsm + 4 * A_STAGE;

    float c[2][8][4];
#pragma unroll
    for (int mt = 0; mt < 2; mt++)
#pragma unroll
        for (int nt = 0; nt < 8; nt++)
#pragma unroll
            for (int q = 0; q < 4; q++) c[mt][nt][q] = 0.f;

    auto issue = [&](int k0, int buf) {
        unsigned ab = smem_u32(As + buf * A_STAGE);
        unsigned bb = smem_u32(Bs + buf * B_STAGE);
#pragma unroll
        for (int it = 0; it < 2; it++) {
            const int f = tid + it * 512;
            const int r = f >> 2, u = f & 3;
            cp16(ab + r * AST + u * 16, A + (size_t)(row0 + r) * DIN + k0 + u * 8);
        }
        {
            const int k = tid >> 4, u = tid & 15;
            cp16(bb + k * 272 + u * 16, B + (size_t)(k0 + k) * DIN + col0 + u * 8);
        }
    };

    issue(0, 0);  CP_COMMIT();
    issue(32, 1); CP_COMMIT();

    const int lrow = (lane & 7) + ((lane >> 3) & 1) * 8;
    const int lcol = ((lane >> 4) & 1) * 8;
    const int aoff = (warp_m + (lane & 15)) * AST + (lane >> 4) * 16;

    for (int kt = 0; kt < 32; kt++) {
        if (kt + 2 < 32) issue((kt + 2) * 32, (kt + 2) & 3);
        CP_COMMIT();
        CP_WAIT2();
        __syncthreads();

        const unsigned ab = smem_u32(As + (kt & 3) * A_STAGE);
        const unsigned bb = smem_u32(Bs + (kt & 3) * B_STAGE);
#pragma unroll
        for (int kc = 0; kc < 2; kc++) {
            unsigned a[2][4];
#pragma unroll
            for (int mt = 0; mt < 2; mt++)
                ldmx4(a[mt][0], a[mt][1], a[mt][2], a[mt][3],
                      ab + aoff + mt * 16 * AST + kc * 32);
#pragma unroll
            for (int p = 0; p < 4; p++) {
                unsigned r0, r1, r2, r3;
                ldmx4t(r0, r1, r2, r3,
                       bb + (kc * 16 + lrow) * 272 + (warp_n + p * 16 + lcol) * 2);
                unsigned b0[2] = {r0, r1}, b1[2] = {r2, r3};
#pragma unroll
                for (int mt = 0; mt < 2; mt++) {
                    MMA_F16(c[mt][2 * p],     a[mt], b0);
                    MMA_F16(c[mt][2 * p + 1], a[mt], b1);
                }
            }
        }
    }

#pragma unroll
    for (int mt = 0; mt < 2; mt++)
#pragma unroll
        for (int nt = 0; nt < 8; nt++) {
            const int cb = col0 + warp_n + nt * 8 + 2 * tig;
#pragma unroll
            for (int hf = 0; hf < 2; hf++) {
                const int r = row0 + warp_m + mt * 16 + gid + 8 * hf;
                O[(size_t)r * DIN + cb]     = c[mt][nt][hf * 2]     + resid[(size_t)r * DIN + cb];
                O[(size_t)r * DIN + cb + 1] = c[mt][nt][hf * 2 + 1] + resid[(size_t)r * DIN + cb + 1];
            }
        }
}

// ============ fused flash attention, FA2 layout (m-split warps) — proven R11 =====
// Block: one (b,h), 128 q-rows, 8 warps each owning 16 full rows.
// smem (96256 B): sK 2x9216 @0 | sV 2x9216 @18432 | P ring 256x144 @36864
//                 sSp 8 x (16 x 88 half) @73728
__global__ __launch_bounds__(256, 2) void flash_attn(
    const __half* __restrict__ qug, const __half* __restrict__ qvg,
    const __half* __restrict__ kg,  const __half* __restrict__ vg,
    const __half* __restrict__ pg,  __half* __restrict__ awv)
{
    char* base = dsm;
    char* sKb = base;
    char* sVb = base + 18432;
    char* sPr = base + 36864;
    const unsigned* Pring = (const unsigned*)sPr;

    const int tid = threadIdx.x;
    const int lane = tid & 31, wid = tid >> 5;
    const int gid = lane >> 2, tig = lane & 3;
    const int i0 = (3 - (int)blockIdx.x) * 128;     // heavy tiles first
    const int bh = blockIdx.y;
    const int b = bh >> 4, h = bh & 15;
    const int lrow = (lane & 7) + ((lane >> 3) & 1) * 8;
    const int lcol = ((lane >> 4) & 1) * 8;
    const int rb0 = 384 - i0;                       // P window base at step 0
    const int nsteps = i0 / 64 + 10;

    __half* sSpW = (__half*)(base + 73728 + wid * 2816);   // 16 x 88 halves

    // ---- prologue: issue step-0 group (P rows rb0..rb0+191, K/V j0=0) ----
    {
#pragma unroll
        for (int it = 0; it < 6; it++) {
            const int f = tid + it * 256;
            const int rl = f >> 3, u = f & 7;
            const int r = rb0 + rl;
            const int slot = r & 255;
            const int src = min(r, TOT - 1);
            cp16(smem_u32(sPr + slot * 144 + u * 16),
                 pg + (size_t)src * DIN + h * HD + u * 8);
        }
        const __half* kb = kg + (size_t)b * DIN + h * HD;
        const __half* vb = vg + (size_t)b * DIN + h * HD;
#pragma unroll
        for (int it = 0; it < 2; it++) {
            const int f = tid + it * 256;
            const int r = f >> 3, u = f & 7;
            cp16(smem_u32(sKb + r * 144 + u * 16), kb + (size_t)r * BSZ * DIN + u * 8);
            cp16(smem_u32(sVb + r * 144 + u * 16), vb + (size_t)r * BSZ * DIN + u * 8);
        }
        CP_COMMIT();
    }

    // ---- Q fragments: load from global into registers (held all kernel) ----
    unsigned qu_f[4][4], qv_f[4][4];
    {
        const int r0 = i0 + wid * 16 + gid;
        const __half* a0 = qug + ((size_t)r0 * BSZ + b) * DIN + h * HD;
        const __half* a8 = a0 + (size_t)8 * BSZ * DIN;
        const __half* v0 = qvg + ((size_t)r0 * BSZ + b) * DIN + h * HD;
        const __half* v8 = v0 + (size_t)8 * BSZ * DIN;
#pragma unroll
        for (int kc = 0; kc < 4; kc++) {
            qu_f[kc][0] = *(const unsigned*)(a0 + kc * 16 + 2 * tig);
            qu_f[kc][1] = *(const unsigned*)(a8 + kc * 16 + 2 * tig);
            qu_f[kc][2] = *(const unsigned*)(a0 + kc * 16 + 8 + 2 * tig);
            qu_f[kc][3] = *(const unsigned*)(a8 + kc * 16 + 8 + 2 * tig);
            qv_f[kc][0] = *(const unsigned*)(v0 + kc * 16 + 2 * tig);
            qv_f[kc][1] = *(const unsigned*)(v8 + kc * 16 + 2 * tig);
            qv_f[kc][2] = *(const unsigned*)(v0 + kc * 16 + 8 + 2 * tig);
            qv_f[kc][3] = *(const unsigned*)(v8 + kc * 16 + 8 + 2 * tig);
        }
    }

    float o[8][4];
#pragma unroll
    for (int nt = 0; nt < 8; nt++)
#pragma unroll
        for (int e = 0; e < 4; e++) o[nt][e] = 0.f;
    float l0 = 0.f, l1 = 0.f;

    for (int s = 0; s < nsteps; s++) {
        const int j0 = s * 64;
        if (s + 1 < nsteps) {
            const int buf = (s + 1) & 1;
            const __half* kb = kg + ((size_t)(j0 + 64) * BSZ + b) * DIN + h * HD;
            const __half* vb = vg + ((size_t)(j0 + 64) * BSZ + b) * DIN + h * HD;
            const unsigned kd = smem_u32(sKb + buf * 9216);
            const unsigned vd = smem_u32(sVb + buf * 9216);
#pragma unroll
            for (int it = 0; it < 2; it++) {
                const int f = tid + it * 256;
                const int r = f >> 3, u = f & 7;
                cp16(kd + r * 144 + u * 16, kb + (size_t)r * BSZ * DIN + u * 8);
                cp16(vd + r * 144 + u * 16, vb + (size_t)r * BSZ * DIN + u * 8);
            }
            const int wb = rb0 + 64 * (s + 1) + 128;   // new 64 P rows for window s+1
#pragma unroll
            for (int it = 0; it < 2; it++) {
                const int f = tid + it * 256;
                const int rl = f >> 3, u = f & 7;
                const int r = wb + rl;
                const int slot = r & 255;
                const int src = min(r, TOT - 1);
                cp16(smem_u32(sPr + slot * 144 + u * 16),
                     pg + (size_t)src * DIN + h * HD + u * 8);
            }
        }
        CP_COMMIT();
        CP_WAIT1();
        __syncthreads();

        const int di = i0 + 16 * wid + 512 - j0;       // mask: lj <= di + li
        if (di + 15 >= 0) {                            // warp has unmasked work
            const unsigned* Ku = (const unsigned*)(sKb + (s & 1) * 9216);
            const unsigned  vB = smem_u32(sVb + (s & 1) * 9216);

            // ---- S_p = Qv_warp(16x64) @ P_slice(80x64)^T, staged in 2 halves ----
            const int rsg = j0 + 496 - i0 - 16 * wid + gid;   // ring row for this gid
#pragma unroll
            for (int half = 0; half < 2; half++) {
                float cp5[5][4];
#pragma unroll
                for (int nt = 0; nt < 5; nt++)
#pragma unroll
                    for (int e = 0; e < 4; e++) cp5[nt][e] = 0.f;
#pragma unroll
                for (int kc = 0; kc < 4; kc++) {
#pragma unroll
                    for (int nt = 0; nt < 5; nt++) {
                        const int slot = (rsg + half * 40 + nt * 8) & 255;
                        unsigned bf[2];
                        bf[0] = Pring[slot * 36 + kc * 8 + tig];
                        bf[1] = Pring[slot * 36 + kc * 8 + tig + 4];
                        MMA_F16(cp5[nt], qv_f[kc], bf);
                    }
                }
#pragma unroll
                for (int nt = 0; nt < 5; nt++) {
                    const int cn = (half * 5 + nt) * 8 + 2 * tig;
                    *(__half2*)&sSpW[gid * 88 + cn] =
                        __floats2half2_rn(cp5[nt][0], cp5[nt][1]);
                    *(__half2*)&sSpW[(gid + 8) * 88 + cn] =
                        __floats2half2_rn(cp5[nt][2], cp5[nt][3]);
                }
            }
            __syncwarp();

            // ---- S_c = Qu_warp(16x64) @ K^T(64x64) ----
            float cc[8][4];
#pragma unroll
            for (int nt = 0; nt < 8; nt++)
#pragma unroll
                for (int e = 0; e < 4; e++) cc[nt][e] = 0.f;
#pragma unroll
            for (int kc = 0; kc < 4; kc++)
#pragma unroll
                for (int nt = 0; nt < 8; nt++) {
                    unsigned bf[2];
                    bf[0] = Ku[(nt * 8 + gid) * 36 + kc * 8 + tig];
                    bf[1] = Ku[(nt * 8 + gid) * 36 + kc * 8 + tig + 4];
                    MMA_F16(cc[nt], qu_f[kc], bf);
                }

            // ---- combine + mask + exp (no-max) + pack; accumulate row sums ----
            unsigned pa[4][4];
            float ls0 = 0.f, ls1 = 0.f;
#pragma unroll
            for (int nt = 0; nt < 8; nt++) {
                const int lj = nt * 8 + 2 * tig;
                const int liA = gid, liB = gid + 8;
                float spA0 = __half2float(sSpW[liA * 88 + lj + 15 - liA]);
                float spA1 = __half2float(sSpW[liA * 88 + lj + 16 - liA]);
                float spB0 = __half2float(sSpW[liB * 88 + lj + 15 - liB]);
                float spB1 = __half2float(sSpW[liB * 88 + lj + 16 - liB]);
                float eA0 = (lj     <= di + liA) ? __expf((cc[nt][0] + spA0) * 0.125f) : 0.f;
                float eA1 = (lj + 1 <= di + liA) ? __expf((cc[nt][1] + spA1) * 0.125f) : 0.f;
                float eB0 = (lj     <= di + liB) ? __expf((cc[nt][2] + spB0) * 0.125f) : 0.f;
                float eB1 = (lj + 1 <= di + liB) ? __expf((cc[nt][3] + spB1) * 0.125f) : 0.f;
                ls0 += eA0 + eA1;
                ls1 += eB0 + eB1;
                __half2 hA = __floats2half2_rn(eA0, eA1);
                __half2 hB = __floats2half2_rn(eB0, eB1);
                pa[nt >> 1][(nt & 1) * 2]     = *(unsigned*)&hA;
                pa[nt >> 1][(nt & 1) * 2 + 1] = *(unsigned*)&hB;
            }
            ls0 += __shfl_xor_sync(0xffffffffu, ls0, 1);
            ls0 += __shfl_xor_sync(0xffffffffu, ls0, 2);
            ls1 += __shfl_xor_sync(0xffffffffu, ls1, 1);
            ls1 += __shfl_xor_sync(0xffffffffu, ls1, 2);
            l0 += ls0; l1 += ls1;

            // ---- O += P @ V (probs already in A-fragment registers) ----
#pragma unroll
            for (int kc = 0; kc < 4; kc++) {
#pragma unroll
                for (int np = 0; np < 4; np++) {
                    unsigned r0, r1, r2, r3;
                    ldmx4t(r0, r1, r2, r3,
                           vB + (kc * 16 + lrow) * 144 + (np * 16 + lcol) * 2);
                    unsigned b0[2] = {r0, r1}, b1[2] = {r2, r3};
                    MMA_F16(o[2 * np],     pa[kc], b0);
                    MMA_F16(o[2 * np + 1], pa[kc], b1);
                }
            }
        }
        __syncthreads();   // buffers + ring + sSp free for next step
    }

    // ---- write awv = O / l (fp16) ----
    const float inv0 = 1.f / l0, inv1 = 1.f / l1;
    const int r0 = i0 + wid * 16 + gid;
#pragma unroll
    for (int nt = 0; nt < 8; nt++) {
        const int c = nt * 8 + 2 * tig;
        *(__half2*)&awv[((size_t)r0 * BSZ + b) * DIN + h * HD + c] =
            __floats2half2_rn(o[nt][0] * inv0, o[nt][1] * inv0);
        *(__half2*)&awv[((size_t)(r0 + 8) * BSZ + b) * DIN + h * HD + c] =
            __floats2half2_rn(o[nt][2] * inv1, o[nt][3] * inv1);
    }
}

// ---------------- LayerNorm over last dim (1024), one block per row ------------
__global__ __launch_bounds__(256) void ln_kernel(
    const float* __restrict__ x, const float* __restrict__ gamma,
    const float* __restrict__ beta, float* __restrict__ out)
{
    const size_t row = blockIdx.x;
    const int tid = threadIdx.x;
    const float4 v = ((const float4*)(x + row * DIN))[tid];
    __shared__ float red[8];

    float s = v.x + v.y + v.z + v.w;
#pragma unroll
    for (int o = 16; o; o >>= 1) s += __shfl_xor_sync(0xffffffffu, s, o);
    if ((tid & 31) == 0) red[tid >> 5] = s;
    __syncthreads();
    s = red[0];
#pragma unroll
    for (int w = 1; w < 8; w++) s += red[w];
    const float mu = s * (1.0f / DIN);
    __syncthreads();

    const float d0 = v.x - mu, d1 = v.y - mu, d2 = v.z - mu, d3 = v.w - mu;
    float s2 = d0 * d0 + d1 * d1 + d2 * d2 + d3 * d3;
#pragma unroll
    for (int o = 16; o; o >>= 1) s2 += __shfl_xor_sync(0xffffffffu, s2, o);
    if ((tid & 31) == 0) red[tid >> 5] = s2;
    __syncthreads();
    s2 = red[0];
#pragma unroll
    for (int w = 1; w < 8; w++) s2 += red[w];
    const float inv = rsqrtf(s2 * (1.0f / DIN) + 1e-5f);

    const float4 g  = ((const float4*)gamma)[tid];
    const float4 bb = ((const float4*)beta)[tid];
    float4 o4;
    o4.x = d0 * inv * g.x + bb.x;
    o4.y = d1 * inv * g.y + bb.y;
    o4.z = d2 * inv * g.z + bb.z;
    o4.w = d3 * inv * g.w + bb.w;
    ((float4*)(out + row * DIN))[tid] = o4;
}

// ---------------- launch ---------------------------------------------------------
extern "C" void kernel_launch(void* const* d_in, const int* in_sizes, int n_in,
                              void* d_out, int out_size)
{
    const float* input_ = (const float*)d_in[0];
    const float* pos    = (const float*)d_in[1];
    const float* memory = (const float*)d_in[2];
    const float* u      = (const float*)d_in[3];
    const float* vvec   = (const float*)d_in[4];
    // d_in[5] = mask (analytic: j <= i + PREV)
    const float* W_kv   = (const float*)d_in[6];
    const float* W_q    = (const float*)d_in[7];
    const float* W_p    = (const float*)d_in[8];
    const float* W_out  = (const float*)d_in[9];
    const float* gamma  = (const float*)d_in[10];
    const float* beta   = (const float*)d_in[11];
    float* out = (float*)d_out;

    __half *pin, *pmem, *ppos, *pwkv, *pwq, *pwp, *pwo;
    __half *pk, *pv, *pp, *pqu, *pqv, *pawv;
    float* pout;
    cudaGetSymbolAddress((void**)&pin,  g_in16);
    cudaGetSymbolAddress((void**)&pmem, g_mem16);
    cudaGetSymbolAddress((void**)&ppos, g_pos16);
    cudaGetSymbolAddress((void**)&pwkv, g_wkv16);
    cudaGetSymbolAddress((void**)&pwq,  g_wq16);
    cudaGetSymbolAddress((void**)&pwp,  g_wp16);
    cudaGetSymbolAddress((void**)&pwo,  g_wo16);
    cudaGetSymbolAddress((void**)&pk,   g_kh);
    cudaGetSymbolAddress((void**)&pv,   g_vh);
    cudaGetSymbolAddress((void**)&pp,   g_ph);
    cudaGetSymbolAddress((void**)&pqu,  g_qu);
    cudaGetSymbolAddress((void**)&pqv,  g_qv);
    cudaGetSymbolAddress((void**)&pawv, g_awv);
    cudaGetSymbolAddress((void**)&pout, g_out);

    const int FA_SMEM = 96256;
    cudaFuncSetAttribute(proj_mega, cudaFuncAttributeMaxDynamicSharedMemorySize, GEMM_SM);
    cudaFuncSetAttribute(out_gemm,  cudaFuncAttributeMaxDynamicSharedMemorySize, GEMM_SM);
    cudaFuncSetAttribute(flash_attn, cudaFuncAttributeMaxDynamicSharedMemorySize, FA_SMEM);

    // 0) fp32 -> fp16 conversions, single launch
    CvtSegs segs;
    segs.src[0] = (const float4*)input_; segs.dst[0] = (__half2*)pin;  segs.n4[0] = SEQ * BSZ * DIN / 4;
    segs.src[1] = (const float4*)memory; segs.dst[1] = (__half2*)pmem; segs.n4[1] = PREV * BSZ * DIN / 4;
    segs.src[2] = (const float4*)pos;    segs.dst[2] = (__half2*)ppos; segs.n4[2] = TOT * DIN / 4;
    segs.src[3] = (const float4*)W_kv;   segs.dst[3] = (__half2*)pwkv; segs.n4[3] = DIN * 2 * DIN / 4;
    segs.src[4] = (const float4*)W_q;    segs.dst[4] = (__half2*)pwq;  segs.n4[4] = DIN * DIN / 4;
    segs.src[5] = (const float4*)W_p;    segs.dst[5] = (__half2*)pwp;  segs.n4[5] = DIN * DIN / 4;
    segs.src[6] = (const float4*)W_out;  segs.dst[6] = (__half2*)pwo;  segs.n4[6] = DIN * DIN / 4;
    int total4 = 0;
    for (int k = 0; k < 7; k++) total4 += segs.n4[k];
    cvt_all<<<(total4 + 255) / 256, 256>>>(segs);

    // 1) all projections (kv | q | p) in one launch (256x128 tiles)
    proj_mega<<<672, 512, GEMM_SM>>>(
        pin, pmem, ppos, pwkv, pwq, pwp,
        pk, pv, pqu, pqv, pp, u, vvec);

    // 2) fused attention -> awv (fp16)
    flash_attn<<<dim3(4, BSZ * NH), 256, FA_SMEM>>>(
        pqu, pqv, pk, pv, pp, pawv);

    // 3) out_pre = input_ + awv @ W_out (fp32) on 256x128 tiles
    out_gemm<<<dim3(8, 16), 512, GEMM_SM>>>(pawv, pwo, pout, input_);

    // 4) LayerNorm -> d_out
    ln_kernel<<<SEQ * BSZ, 256>>>(pout, gamma, beta, out);
}

// round 17
// speedup vs baseline: 1.0832x; 1.0832x over previous
#include <cuda_runtime.h>
#include <cuda_fp16.h>
#include <math.h>

#define SEQ  512
#define PREV 512
#define TOT  1024
#define BSZ  8
#define DIN  1024
#define NH   16
#define HD   64

// ---------------- scratch (static device globals; no allocations) ----------------
__device__ __half g_in16 [SEQ * BSZ * DIN];
__device__ __half g_mem16[PREV * BSZ * DIN];
__device__ __half g_pos16[TOT * DIN];
__device__ __half g_wkv16[DIN * 2 * DIN];
__device__ __half g_wq16 [DIN * DIN];
__device__ __half g_wp16 [DIN * DIN];
__device__ __half g_wo16 [DIN * DIN];
__device__ __half g_kh [TOT * BSZ * DIN];
__device__ __half g_vh [TOT * BSZ * DIN];
__device__ __half g_ph [TOT * DIN];
__device__ __half g_qu [SEQ * BSZ * DIN];
__device__ __half g_qv [SEQ * BSZ * DIN];
__device__ __half g_awv[SEQ * BSZ * DIN];
__device__ float  g_out[SEQ * BSZ * DIN];

__device__ __forceinline__ unsigned smem_u32(const void* p) {
    return (unsigned)__cvta_generic_to_shared(p);
}
__device__ __forceinline__ void cp16(unsigned dst, const void* src) {
    asm volatile("cp.async.cg.shared.global [%0], [%1], 16;" :: "r"(dst), "l"(src));
}
#define CP_COMMIT() asm volatile("cp.async.commit_group;")
#define CP_WAIT1()  asm volatile("cp.async.wait_group 1;")
#define CP_WAIT2()  asm volatile("cp.async.wait_group 2;")

#define MMA_F16(c, a, b)                                                       \
    asm volatile(                                                              \
        "mma.sync.aligned.m16n8k16.row.col.f32.f16.f16.f32 "                   \
        "{%0,%1,%2,%3},{%4,%5,%6,%7},{%8,%9},{%0,%1,%2,%3};"                   \
        : "+f"(c[0]), "+f"(c[1]), "+f"(c[2]), "+f"(c[3])                       \
        : "r"(a[0]), "r"(a[1]), "r"(a[2]), "r"(a[3]), "r"(b[0]), "r"(b[1]))

__device__ __forceinline__ void ldmx4t(unsigned& r0, unsigned& r1,
                                       unsigned& r2, unsigned& r3, unsigned a) {
    asm volatile("ldmatrix.sync.aligned.m8n8.x4.trans.shared.b16 "
                 "{%0,%1,%2,%3}, [%4];"
                 : "=r"(r0), "=r"(r1), "=r"(r2), "=r"(r3) : "r"(a));
}
__device__ __forceinline__ void ldmx4(unsigned& r0, unsigned& r1,
                                      unsigned& r2, unsigned& r3, unsigned a) {
    asm volatile("ldmatrix.sync.aligned.m8n8.x4.shared.b16 "
                 "{%0,%1,%2,%3}, [%4];"
                 : "=r"(r0), "=r"(r1), "=r"(r2), "=r"(r3) : "r"(a));
}

// ---------------- fp32 -> fp16 converter (single segmented launch) --------------
struct CvtSegs {
    const float4* src[7];
    __half2*      dst[7];
    int           n4[7];
};

__global__ void cvt_all(CvtSegs s)
{
    int i = blockIdx.x * blockDim.x + threadIdx.x;
#pragma unroll
    for (int k = 0; k < 7; k++) {
        if (i < s.n4[k]) {
            float4 v = s.src[k][i];
            s.dst[k][2 * i]     = __floats2half2_rn(v.x, v.y);
            s.dst[k][2 * i + 1] = __floats2half2_rn(v.z, v.w);
            return;
        }
        i -= s.n4[k];
    }
}

extern __shared__ char dsm[];

// A stage: 128 rows x 80 B (stride 80 = 16-aligned, ldmatrix conflict-free).
// B stage: 32 rows x 272 B. 4 pipeline stages, prefetch distance 2.  (R11 proven)
#define AST 80
#define A_STAGE (128 * AST)    // 10240
#define B_STAGE (32 * 272)     // 8704
#define GEMM_SM (4 * (A_STAGE + B_STAGE))   // 75776

// ============ mega projection GEMM: kv + q + p in ONE launch (R11 proven) ========
// blockIdx.x < 1024 : kv  (M=8192 gather(mem|in), N=2048, split -> kh|vh)
// 1024..1279        : q   (M=4096 in,            N=1024, dual bias -> qu,qv)
// 1280..1343        : p   (M=1024 pos,           N=1024, plain -> ph)
__global__ __launch_bounds__(256, 2) void proj_mega(
    const __half* __restrict__ in16, const __half* __restrict__ mem16,
    const __half* __restrict__ pos16,
    const __half* __restrict__ wkv, const __half* __restrict__ wq,
    const __half* __restrict__ wp,
    __half* __restrict__ kh, __half* __restrict__ vh,
    __half* __restrict__ quo, __half* __restrict__ qvo,
    __half* __restrict__ ph,
    const float* __restrict__ ubias, const float* __restrict__ vbias)
{
    const int bx = blockIdx.x;
    const __half *A0, *A1, *B;
    int M0, row0, col0, epi;
    long ldb;
    if (bx < 1024) {
        row0 = (bx >> 4) * 128; col0 = (bx & 15) * 128;
        A0 = mem16; A1 = in16; M0 = PREV * BSZ; B = wkv; ldb = 2 * DIN; epi = 1;
    } else if (bx < 1280) {
        const int t = bx - 1024;
        row0 = (t >> 3) * 128; col0 = (t & 7) * 128;
        A0 = in16; A1 = in16; M0 = 1 << 30; B = wq; ldb = DIN; epi = 2;
    } else {
        const int t = bx - 1280;
        row0 = (t >> 3) * 128; col0 = (t & 7) * 128;
        A0 = pos16; A1 = pos16; M0 = 1 << 30; B = wp; ldb = DIN; epi = 3;
    }

    const int tid  = threadIdx.x;
    const int lane = tid & 31, wid = tid >> 5;
    const int gid  = lane >> 2, tig = lane & 3;
    const int warp_m = (wid & 3) * 32;
    const int warp_n = (wid >> 2) * 64;

    char* As = dsm;                   // 4 x A_STAGE
    char* Bs = dsm + 4 * A_STAGE;     // 4 x B_STAGE

    float c[2][8][4];
#pragma unroll
    for (int mt = 0; mt < 2; mt++)
#pragma unroll
        for (int nt = 0; nt < 8; nt++)
#pragma unroll
            for (int q = 0; q < 4; q++) c[mt][nt][q] = 0.f;

    auto issue = [&](int k0, int buf) {
        unsigned ab = smem_u32(As + buf * A_STAGE);
        unsigned bb = smem_u32(Bs + buf * B_STAGE);
#pragma unroll
        for (int it = 0; it < 2; it++) {
            const int f = tid + it * 256;
            const int r = f >> 2, u = f & 3;
            const int gm = row0 + r;
            const __half* src = (gm < M0 ? A0 + (size_t)gm * DIN
                                         : A1 + (size_t)(gm - M0) * DIN) + k0 + u * 8;
            cp16(ab + r * AST + u * 16, src);
        }
#pragma unroll
        for (int it = 0; it < 2; it++) {
            const int f = tid + it * 256;
            const int k = f >> 4, u = f & 15;
            cp16(bb + k * 272 + u * 16, B + (size_t)(k0 + k) * ldb + col0 + u * 8);
        }
    };

    issue(0, 0);  CP_COMMIT();
    issue(32, 1); CP_COMMIT();

    const int lrow = (lane & 7) + ((lane >> 3) & 1) * 8;
    const int lcol = ((lane >> 4) & 1) * 8;
    const int aoff = (warp_m + (lane & 15)) * AST + (lane >> 4) * 16;

    for (int kt = 0; kt < 32; kt++) {
        if (kt + 2 < 32) issue((kt + 2) * 32, (kt + 2) & 3);
        CP_COMMIT();
        CP_WAIT2();
        __syncthreads();

        const unsigned ab = smem_u32(As + (kt & 3) * A_STAGE);
        const unsigned bb = smem_u32(Bs + (kt & 3) * B_STAGE);
#pragma unroll
        for (int kc = 0; kc < 2; kc++) {
            unsigned a[2][4];
#pragma unroll
            for (int mt = 0; mt < 2; mt++)
                ldmx4(a[mt][0], a[mt][1], a[mt][2], a[mt][3],
                      ab + aoff + mt * 16 * AST + kc * 32);
#pragma unroll
            for (int p = 0; p < 4; p++) {
                unsigned r0, r1, r2, r3;
                ldmx4t(r0, r1, r2, r3,
                       bb + (kc * 16 + lrow) * 272 + (warp_n + p * 16 + lcol) * 2);
                unsigned b0[2] = {r0, r1}, b1[2] = {r2, r3};
#pragma unroll
                for (int mt = 0; mt < 2; mt++) {
                    MMA_F16(c[mt][2 * p],     a[mt], b0);
                    MMA_F16(c[mt][2 * p + 1], a[mt], b1);
                }
            }
        }
    }

#pragma unroll
    for (int mt = 0; mt < 2; mt++) {
#pragma unroll
        for (int nt = 0; nt < 8; nt++) {
            const int cb = col0 + warp_n + nt * 8 + 2 * tig;
#pragma unroll
            for (int hf = 0; hf < 2; hf++) {
                const int r = row0 + warp_m + mt * 16 + gid + 8 * hf;
                float v0 = c[mt][nt][hf * 2], v1 = c[mt][nt][hf * 2 + 1];
                if (epi == 1) {
                    __half2 h = __floats2half2_rn(v0, v1);
                    if (cb < DIN)
                        *(__half2*)(kh + (size_t)r * DIN + cb) = h;
                    else
                        *(__half2*)(vh + (size_t)r * DIN + cb - DIN) = h;
                } else if (epi == 2) {
                    *(__half2*)(quo + (size_t)r * DIN + cb) =
                        __floats2half2_rn(v0 + ubias[cb], v1 + ubias[cb + 1]);
                    *(__half2*)(qvo + (size_t)r * DIN + cb) =
                        __floats2half2_rn(v0 + vbias[cb], v1 + vbias[cb + 1]);
                } else {
                    *(__half2*)(ph + (size_t)r * DIN + cb) =
                        __floats2half2_rn(v0, v1);
                }
            }
        }
    }
}

// ============ output projection GEMM (fp32 out + residual), R11 proven ===========
__global__ __launch_bounds__(256, 2) void out_gemm(
    const __half* __restrict__ A, const __half* __restrict__ B,
    float* __restrict__ O, const float* __restrict__ resid)
{
    const int tid  = threadIdx.x;
    const int lane = tid & 31, wid = tid >> 5;
    const int gid  = lane >> 2, tig = lane & 3;
    const int warp_m = (wid & 3) * 32;
    const int warp_n = (wid >> 2) * 64;
    const int row0 = blockIdx.y * 128;
    const int col0 = blockIdx.x * 128;

    char* As = dsm;
    char* Bs = dsm + 4 * A_STAGE;

    float c[2][8][4];
#pragma unroll
    for (int mt = 0; mt < 2; mt++)
#pragma unroll
        for (int nt = 0; nt < 8; nt++)
#pragma unroll
            for (int q = 0; q < 4; q++) c[mt][nt][q] = 0.f;

    auto issue = [&](int k0, int buf) {
        unsigned ab = smem_u32(As + buf * A_STAGE);
        unsigned bb = smem_u32(Bs + buf * B_STAGE);
#pragma unroll
        for (int it = 0; it < 2; it++) {
            const int f = tid + it * 256;
            const int r = f >> 2, u = f & 3;
            cp16(ab + r * AST + u * 16, A + (size_t)(row0 + r) * DIN + k0 + u * 8);
        }
#pragma unroll
        for (int it = 0; it < 2; it++) {
            const int f = tid + it * 256;
            const int k = f >> 4, u = f & 15;
            cp16(bb + k * 272 + u * 16, B + (size_t)(k0 + k) * DIN + col0 + u * 8);
        }
    };

    issue(0, 0);  CP_COMMIT();
    issue(32, 1); CP_COMMIT();

    const int lrow = (lane & 7) + ((lane >> 3) & 1) * 8;
    const int lcol = ((lane >> 4) & 1) * 8;
    const int aoff = (warp_m + (lane & 15)) * AST + (lane >> 4) * 16;

    for (int kt = 0; kt < 32; kt++) {
        if (kt + 2 < 32) issue((kt + 2) * 32, (kt + 2) & 3);
        CP_COMMIT();
        CP_WAIT2();
        __syncthreads();

        const unsigned ab = smem_u32(As + (kt & 3) * A_STAGE);
        const unsigned bb = smem_u32(Bs + (kt & 3) * B_STAGE);
#pragma unroll
        for (int kc = 0; kc < 2; kc++) {
            unsigned a[2][4];
#pragma unroll
            for (int mt = 0; mt < 2; mt++)
                ldmx4(a[mt][0], a[mt][1], a[mt][2], a[mt][3],
                      ab + aoff + mt * 16 * AST + kc * 32);
#pragma unroll
            for (int p = 0; p < 4; p++) {
                unsigned r0, r1, r2, r3;
                ldmx4t(r0, r1, r2, r3,
                       bb + (kc * 16 + lrow) * 272 + (warp_n + p * 16 + lcol) * 2);
                unsigned b0[2] = {r0, r1}, b1[2] = {r2, r3};
#pragma unroll
                for (int mt = 0; mt < 2; mt++) {
                    MMA_F16(c[mt][2 * p],     a[mt], b0);
                    MMA_F16(c[mt][2 * p + 1], a[mt], b1);
                }
            }
        }
    }

#pragma unroll
    for (int mt = 0; mt < 2; mt++)
#pragma unroll
        for (int nt = 0; nt < 8; nt++) {
            const int cb = col0 + warp_n + nt * 8 + 2 * tig;
#pragma unroll
            for (int hf = 0; hf < 2; hf++) {
                const int r = row0 + warp_m + mt * 16 + gid + 8 * hf;
                O[(size_t)r * DIN + cb]     = c[mt][nt][hf * 2]     + resid[(size_t)r * DIN + cb];
                O[(size_t)r * DIN + cb + 1] = c[mt][nt][hf * 2 + 1] + resid[(size_t)r * DIN + cb + 1];
            }
        }
}

// ============ fused flash attention, FA2 layout (m-split warps) — proven R11 =====
// Block: one (b,h), 128 q-rows, 8 warps each owning 16 full rows.
// smem (96256 B): sK 2x9216 @0 | sV 2x9216 @18432 | P ring 256x144 @36864
//                 sSp 8 x (16 x 88 half) @73728
__global__ __launch_bounds__(256, 2) void flash_attn(
    const __half* __restrict__ qug, const __half* __restrict__ qvg,
    const __half* __restrict__ kg,  const __half* __restrict__ vg,
    const __half* __restrict__ pg,  __half* __restrict__ awv)
{
    char* base = dsm;
    char* sKb = base;
    char* sVb = base + 18432;
    char* sPr = base + 36864;
    const unsigned* Pring = (const unsigned*)sPr;

    const int tid = threadIdx.x;
    const int lane = tid & 31, wid = tid >> 5;
    const int gid = lane >> 2, tig = lane & 3;
    const int i0 = (3 - (int)blockIdx.x) * 128;     // heavy tiles first
    const int bh = blockIdx.y;
    const int b = bh >> 4, h = bh & 15;
    const int lrow = (lane & 7) + ((lane >> 3) & 1) * 8;
    const int lcol = ((lane >> 4) & 1) * 8;
    const int rb0 = 384 - i0;                       // P window base at step 0
    const int nsteps = i0 / 64 + 10;

    __half* sSpW = (__half*)(base + 73728 + wid * 2816);   // 16 x 88 halves

    // ---- prologue: issue step-0 group (P rows rb0..rb0+191, K/V j0=0) ----
    {
#pragma unroll
        for (int it = 0; it < 6; it++) {
            const int f = tid + it * 256;
            const int rl = f >> 3, u = f & 7;
            const int r = rb0 + rl;
            const int slot = r & 255;
            const int src = min(r, TOT - 1);
            cp16(smem_u32(sPr + slot * 144 + u * 16),
                 pg + (size_t)src * DIN + h * HD + u * 8);
        }
        const __half* kb = kg + (size_t)b * DIN + h * HD;
        const __half* vb = vg + (size_t)b * DIN + h * HD;
#pragma unroll
        for (int it = 0; it < 2; it++) {
            const int f = tid + it * 256;
            const int r = f >> 3, u = f & 7;
            cp16(smem_u32(sKb + r * 144 + u * 16), kb + (size_t)r * BSZ * DIN + u * 8);
            cp16(smem_u32(sVb + r * 144 + u * 16), vb + (size_t)r * BSZ * DIN + u * 8);
        }
        CP_COMMIT();
    }

    // ---- Q fragments: load from global into registers (held all kernel) ----
    unsigned qu_f[4][4], qv_f[4][4];
    {
        const int r0 = i0 + wid * 16 + gid;
        const __half* a0 = qug + ((size_t)r0 * BSZ + b) * DIN + h * HD;
        const __half* a8 = a0 + (size_t)8 * BSZ * DIN;
        const __half* v0 = qvg + ((size_t)r0 * BSZ + b) * DIN + h * HD;
        const __half* v8 = v0 + (size_t)8 * BSZ * DIN;
#pragma unroll
        for (int kc = 0; kc < 4; kc++) {
            qu_f[kc][0] = *(const unsigned*)(a0 + kc * 16 + 2 * tig);
            qu_f[kc][1] = *(const unsigned*)(a8 + kc * 16 + 2 * tig);
            qu_f[kc][2] = *(const unsigned*)(a0 + kc * 16 + 8 + 2 * tig);
            qu_f[kc][3] = *(const unsigned*)(a8 + kc * 16 + 8 + 2 * tig);
            qv_f[kc][0] = *(const unsigned*)(v0 + kc * 16 + 2 * tig);
            qv_f[kc][1] = *(const unsigned*)(v8 + kc * 16 + 2 * tig);
            qv_f[kc][2] = *(const unsigned*)(v0 + kc * 16 + 8 + 2 * tig);
            qv_f[kc][3] = *(const unsigned*)(v8 + kc * 16 + 8 + 2 * tig);
        }
    }

    float o[8][4];
#pragma unroll
    for (int nt = 0; nt < 8; nt++)
#pragma unroll
        for (int e = 0; e < 4; e++) o[nt][e] = 0.f;
    float l0 = 0.f, l1 = 0.f;

    for (int s = 0; s < nsteps; s++) {
        const int j0 = s * 64;
        if (s + 1 < nsteps) {
            const int buf = (s + 1) & 1;
            const __half* kb = kg + ((size_t)(j0 + 64) * BSZ + b) * DIN + h * HD;
            const __half* vb = vg + ((size_t)(j0 + 64) * BSZ + b) * DIN + h * HD;
            const unsigned kd = smem_u32(sKb + buf * 9216);
            const unsigned vd = smem_u32(sVb + buf * 9216);
#pragma unroll
            for (int it = 0; it < 2; it++) {
                const int f = tid + it * 256;
                const int r = f >> 3, u = f & 7;
                cp16(kd + r * 144 + u * 16, kb + (size_t)r * BSZ * DIN + u * 8);
                cp16(vd + r * 144 + u * 16, vb + (size_t)r * BSZ * DIN + u * 8);
            }
            const int wb = rb0 + 64 * (s + 1) + 128;   // new 64 P rows for window s+1
#pragma unroll
            for (int it = 0; it < 2; it++) {
                const int f = tid + it * 256;
                const int rl = f >> 3, u = f & 7;
                const int r = wb + rl;
                const int slot = r & 255;
                const int src = min(r, TOT - 1);
                cp16(smem_u32(sPr + slot * 144 + u * 16),
                     pg + (size_t)src * DIN + h * HD + u * 8);
            }
        }
        CP_COMMIT();
        CP_WAIT1();
        __syncthreads();

        const int di = i0 + 16 * wid + 512 - j0;       // mask: lj <= di + li
        if (di + 15 >= 0) {                            // warp has unmasked work
            const unsigned* Ku = (const unsigned*)(sKb + (s & 1) * 9216);
            const unsigned  vB = smem_u32(sVb + (s & 1) * 9216);

            // ---- S_p = Qv_warp(16x64) @ P_slice(80x64)^T, staged in 2 halves ----
            const int rsg = j0 + 496 - i0 - 16 * wid + gid;   // ring row for this gid
#pragma unroll
            for (int half = 0; half < 2; half++) {
                float cp5[5][4];
#pragma unroll
                for (int nt = 0; nt < 5; nt++)
#pragma unroll
                    for (int e = 0; e < 4; e++) cp5[nt][e] = 0.f;
#pragma unroll
                for (int kc = 0; kc < 4; kc++) {
#pragma unroll
                    for (int nt = 0; nt < 5; nt++) {
                        const int slot = (rsg + half * 40 + nt * 8) & 255;
                        unsigned bf[2];
                        bf[0] = Pring[slot * 36 + kc * 8 + tig];
                        bf[1] = Pring[slot * 36 + kc * 8 + tig + 4];
                        MMA_F16(cp5[nt], qv_f[kc], bf);
                    }
                }
#pragma unroll
                for (int nt = 0; nt < 5; nt++) {
                    const int cn = (half * 5 + nt) * 8 + 2 * tig;
                    *(__half2*)&sSpW[gid * 88 + cn] =
                        __floats2half2_rn(cp5[nt][0], cp5[nt][1]);
                    *(__half2*)&sSpW[(gid + 8) * 88 + cn] =
                        __floats2half2_rn(cp5[nt][2], cp5[nt][3]);
                }
            }
            __syncwarp();

            // ---- S_c = Qu_warp(16x64) @ K^T(64x64) ----
            float cc[8][4];
#pragma unroll
            for (int nt = 0; nt < 8; nt++)
#pragma unroll
                for (int e = 0; e < 4; e++) cc[nt][e] = 0.f;
#pragma unroll
            for (int kc = 0; kc < 4; kc++)
#pragma unroll
                for (int nt = 0; nt < 8; nt++) {
                    unsigned bf[2];
                    bf[0] = Ku[(nt * 8 + gid) * 36 + kc * 8 + tig];
                    bf[1] = Ku[(nt * 8 + gid) * 36 + kc * 8 + tig + 4];
                    MMA_F16(cc[nt], qu_f[kc], bf);
                }

            // ---- combine + mask + exp (no-max) + pack; accumulate row sums ----
            unsigned pa[4][4];
            float ls0 = 0.f, ls1 = 0.f;
#pragma unroll
            for (int nt = 0; nt < 8; nt++) {
                const int lj = nt * 8 + 2 * tig;
                const int liA = gid, liB = gid + 8;
                float spA0 = __half2float(sSpW[liA * 88 + lj + 15 - liA]);
                float spA1 = __half2float(sSpW[liA * 88 + lj + 16 - liA]);
                float spB0 = __half2float(sSpW[liB * 88 + lj + 15 - liB]);
                float spB1 = __half2float(sSpW[liB * 88 + lj + 16 - liB]);
                float eA0 = (lj     <= di + liA) ? __expf((cc[nt][0] + spA0) * 0.125f) : 0.f;
                float eA1 = (lj + 1 <= di + liA) ? __expf((cc[nt][1] + spA1) * 0.125f) : 0.f;
                float eB0 = (lj     <= di + liB) ? __expf((cc[nt][2] + spB0) * 0.125f) : 0.f;
                float eB1 = (lj + 1 <= di + liB) ? __expf((cc[nt][3] + spB1) * 0.125f) : 0.f;
                ls0 += eA0 + eA1;
                ls1 += eB0 + eB1;
                __half2 hA = __floats2half2_rn(eA0, eA1);
                __half2 hB = __floats2half2_rn(eB0, eB1);
                pa[nt >> 1][(nt & 1) * 2]     = *(unsigned*)&hA;
                pa[nt >> 1][(nt & 1) * 2 + 1] = *(unsigned*)&hB;
            }
            ls0 += __shfl_xor_sync(0xffffffffu, ls0, 1);
            ls0 += __shfl_xor_sync(0xffffffffu, ls0, 2);
            ls1 += __shfl_xor_sync(0xffffffffu, ls1, 1);
            ls1 += __shfl_xor_sync(0xffffffffu, ls1, 2);
            l0 += ls0; l1 += ls1;

            // ---- O += P @ V (probs already in A-fragment registers) ----
#pragma unroll
            for (int kc = 0; kc < 4; kc++) {
#pragma unroll
                for (int np = 0; np < 4; np++) {
                    unsigned r0, r1, r2, r3;
                    ldmx4t(r0, r1, r2, r3,
                           vB + (kc * 16 + lrow) * 144 + (np * 16 + lcol) * 2);
                    unsigned b0[2] = {r0, r1}, b1[2] = {r2, r3};
                    MMA_F16(o[2 * np],     pa[kc], b0);
                    MMA_F16(o[2 * np + 1], pa[kc], b1);
                }
            }
        }
        __syncthreads();   // buffers + ring + sSp free for next step
    }

    // ---- write awv = O / l (fp16) ----
    const float inv0 = 1.f / l0, inv1 = 1.f / l1;
    const int r0 = i0 + wid * 16 + gid;
#pragma unroll
    for (int nt = 0; nt < 8; nt++) {
        const int c = nt * 8 + 2 * tig;
        *(__half2*)&awv[((size_t)r0 * BSZ + b) * DIN + h * HD + c] =
            __floats2half2_rn(o[nt][0] * inv0, o[nt][1] * inv0);
        *(__half2*)&awv[((size_t)(r0 + 8) * BSZ + b) * DIN + h * HD + c] =
            __floats2half2_rn(o[nt][2] * inv1, o[nt][3] * inv1);
    }
}

// ---------------- LayerNorm: ONE WARP PER ROW (no block barriers) ---------------
// grid 512 x 256 threads: 8 rows per block, lane holds 32 elems (8 x float4).
__global__ __launch_bounds__(256) void ln_kernel(
    const float* __restrict__ x, const float* __restrict__ gamma,
    const float* __restrict__ beta, float* __restrict__ out)
{
    const int lane = threadIdx.x & 31;
    const size_t row = (size_t)blockIdx.x * 8 + (threadIdx.x >> 5);
    const float4* xp = (const float4*)(x + row * DIN);

    float4 v[8];
    float s = 0.f;
#pragma unroll
    for (int i = 0; i < 8; i++) {
        v[i] = xp[lane + i * 32];
        s += (v[i].x + v[i].y) + (v[i].z + v[i].w);
    }
#pragma unroll
    for (int o = 16; o; o >>= 1) s += __shfl_xor_sync(0xffffffffu, s, o);
    const float mu = s * (1.0f / DIN);

    float s2 = 0.f;
#pragma unroll
    for (int i = 0; i < 8; i++) {
        v[i].x -= mu; v[i].y -= mu; v[i].z -= mu; v[i].w -= mu;
        s2 += (v[i].x * v[i].x + v[i].y * v[i].y)
            + (v[i].z * v[i].z + v[i].w * v[i].w);
    }
#pragma unroll
    for (int o = 16; o; o >>= 1) s2 += __shfl_xor_sync(0xffffffffu, s2, o);
    const float inv = rsqrtf(s2 * (1.0f / DIN) + 1e-5f);

    float4* op = (float4*)(out + row * DIN);
#pragma unroll
    for (int i = 0; i < 8; i++) {
        const float4 g  = ((const float4*)gamma)[lane + i * 32];
        const float4 bb = ((const float4*)beta)[lane + i * 32];
        float4 o4;
        o4.x = v[i].x * inv * g.x + bb.x;
        o4.y = v[i].y * inv * g.y + bb.y;
        o4.z = v[i].z * inv * g.z + bb.z;
        o4.w = v[i].w * inv * g.w + bb.w;
        op[lane + i * 32] = o4;
    }
}

// ---------------- launch ---------------------------------------------------------
extern "C" void kernel_launch(void* const* d_in, const int* in_sizes, int n_in,
                              void* d_out, int out_size)
{
    const float* input_ = (const float*)d_in[0];
    const float* pos    = (const float*)d_in[1];
    const float* memory = (const float*)d_in[2];
    const float* u      = (const float*)d_in[3];
    const float* vvec   = (const float*)d_in[4];
    // d_in[5] = mask (analytic: j <= i + PREV)
    const float* W_kv   = (const float*)d_in[6];
    const float* W_q    = (const float*)d_in[7];
    const float* W_p    = (const float*)d_in[8];
    const float* W_out  = (const float*)d_in[9];
    const float* gamma  = (const float*)d_in[10];
    const float* beta   = (const float*)d_in[11];
    float* out = (float*)d_out;

    __half *pin, *pmem, *ppos, *pwkv, *pwq, *pwp, *pwo;
    __half *pk, *pv, *pp, *pqu, *pqv, *pawv;
    float* pout;
    cudaGetSymbolAddress((void**)&pin,  g_in16);
    cudaGetSymbolAddress((void**)&pmem, g_mem16);
    cudaGetSymbolAddress((void**)&ppos, g_pos16);
    cudaGetSymbolAddress((void**)&pwkv, g_wkv16);
    cudaGetSymbolAddress((void**)&pwq,  g_wq16);
    cudaGetSymbolAddress((void**)&pwp,  g_wp16);
    cudaGetSymbolAddress((void**)&pwo,  g_wo16);
    cudaGetSymbolAddress((void**)&pk,   g_kh);
    cudaGetSymbolAddress((void**)&pv,   g_vh);
    cudaGetSymbolAddress((void**)&pp,   g_ph);
    cudaGetSymbolAddress((void**)&pqu,  g_qu);
    cudaGetSymbolAddress((void**)&pqv,  g_qv);
    cudaGetSymbolAddress((void**)&pawv, g_awv);
    cudaGetSymbolAddress((void**)&pout, g_out);

    const int FA_SMEM = 96256;
    cudaFuncSetAttribute(proj_mega, cudaFuncAttributeMaxDynamicSharedMemorySize, GEMM_SM);
    cudaFuncSetAttribute(out_gemm,  cudaFuncAttributeMaxDynamicSharedMemorySize, GEMM_SM);
    cudaFuncSetAttribute(flash_attn, cudaFuncAttributeMaxDynamicSharedMemorySize, FA_SMEM);

    // 0) fp32 -> fp16 conversions, single launch
    CvtSegs segs;
    segs.src[0] = (const float4*)input_; segs.dst[0] = (__half2*)pin;  segs.n4[0] = SEQ * BSZ * DIN / 4;
    segs.src[1] = (const float4*)memory; segs.dst[1] = (__half2*)pmem; segs.n4[1] = PREV * BSZ * DIN / 4;
    segs.src[2] = (const float4*)pos;    segs.dst[2] = (__half2*)ppos; segs.n4[2] = TOT * DIN / 4;
    segs.src[3] = (const float4*)W_kv;   segs.dst[3] = (__half2*)pwkv; segs.n4[3] = DIN * 2 * DIN / 4;
    segs.src[4] = (const float4*)W_q;    segs.dst[4] = (__half2*)pwq;  segs.n4[4] = DIN * DIN / 4;
    segs.src[5] = (const float4*)W_p;    segs.dst[5] = (__half2*)pwp;  segs.n4[5] = DIN * DIN / 4;
    segs.src[6] = (const float4*)W_out;  segs.dst[6] = (__half2*)pwo;  segs.n4[6] = DIN * DIN / 4;
    int total4 = 0;
    for (int k = 0; k < 7; k++) total4 += segs.n4[k];
    cvt_all<<<(total4 + 255) / 256, 256>>>(segs);

    // 1) all projections (kv | q | p) in one launch (R11 128x128 tiles)
    proj_mega<<<1344, 256, GEMM_SM>>>(
        pin, pmem, ppos, pwkv, pwq, pwp,
        pk, pv, pqu, pqv, pp, u, vvec);

    // 2) fused attention -> awv (fp16)
    flash_attn<<<dim3(4, BSZ * NH), 256, FA_SMEM>>>(
        pqu, pqv, pk, pv, pp, pawv);

    // 3) out_pre = input_ + awv @ W_out (fp32)
    out_gemm<<<dim3(8, 32), 256, GEMM_SM>>>(pawv, pwo, pout, input_);

    // 4) LayerNorm (warp-per-row) -> d_out
    ln_kernel<<<SEQ * BSZ / 8, 256>>>(pout, gamma, beta, out);
}